// round 11
// baseline (speedup 1.0000x reference)
#include <cuda_runtime.h>
#include <cuda_bf16.h>
#include <math.h>
#include <stdint.h>

#define NB 8192
#define ND 256
#define NPOS 8
#define RS 528           // smem row stride bytes (256 bf16 + 8 pad)
#define TILE_B (128 * RS)
#define NTHREADS 1024

__device__ __align__(16) __nv_bfloat16 g_zb[NB * ND];
__device__ float g_pSpd[8 * NB], g_pSneg[8 * NB], g_pTneg[8 * NB];
__device__ float g_pos_s[NB * NPOS], g_lse[NB];
__device__ float g_it;
__device__ unsigned g_negmin_e, g_negmax_e, g_pvmin_e, g_pvmax_e;

__device__ __forceinline__ unsigned encf(float f) {
    unsigned u = __float_as_uint(f);
    return (u & 0x80000000u) ? ~u : (u | 0x80000000u);
}
__device__ __forceinline__ float decf2(unsigned e) {
    unsigned u = (e & 0x80000000u) ? (e ^ 0x80000000u) : ~e;
    return __uint_as_float(u);
}

#define CP16(s, g)  asm volatile("cp.async.cg.shared.global [%0], [%1], 16;" :: "r"(s), "l"(g))
#define CP_COMMIT() asm volatile("cp.async.commit_group;" ::: "memory")
#define CP_WAIT(n)  asm volatile("cp.async.wait_group %0;" :: "n"(n) : "memory")

__device__ __forceinline__ uint32_t smem_u32(const void* p) {
    uint32_t a;
    asm("{ .reg .u64 t; cvta.to.shared.u64 t, %1; cvt.u32.u64 %0, t; }" : "=r"(a) : "l"(p));
    return a;
}

#define LDSM4(r0, r1, r2, r3, a) \
    asm volatile("ldmatrix.sync.aligned.m8n8.x4.shared.b16 {%0,%1,%2,%3}, [%4];" \
        : "=r"(r0), "=r"(r1), "=r"(r2), "=r"(r3) : "r"(a))

#define MMA(d, A0, A1, A2, A3, B0, B1) \
    asm volatile("mma.sync.aligned.m16n8k16.row.col.f32.bf16.bf16.f32 " \
        "{%0,%1,%2,%3},{%4,%5,%6,%7},{%8,%9},{%0,%1,%2,%3};" \
        : "+f"((d)[0]), "+f"((d)[1]), "+f"((d)[2]), "+f"((d)[3]) \
        : "r"(A0), "r"(A1), "r"(A2), "r"(A3), "r"(B0), "r"(B1))

// ---------------- small kernels ----------------
__global__ void k_init(const float* __restrict__ temp) {
    float sp = log1pf(expf(temp[0]));
    g_it = 1.0f / sp;
    g_negmin_e = 0xFFFFFFFFu; g_negmax_e = 0u;
    g_pvmin_e = 0xFFFFFFFFu;  g_pvmax_e = 0u;
}

__global__ void k_norm(const float* __restrict__ emb) {
    int row = blockIdx.x, t = threadIdx.x;
    float x = emb[row * ND + t];
    float s = x * x;
    #pragma unroll
    for (int o = 16; o > 0; o >>= 1) s += __shfl_xor_sync(0xFFFFFFFFu, s, o);
    __shared__ float ws[8];
    if ((t & 31) == 0) ws[t >> 5] = s;
    __syncthreads();
    float tot = 0.f;
    #pragma unroll
    for (int i = 0; i < 8; i++) tot += ws[i];
    g_zb[row * ND + t] = __float2bfloat16(x / fmaxf(sqrtf(tot), 1e-12f));
}

__global__ void k_pvminmax(const float* __restrict__ pv) {
    int i = blockIdx.x * blockDim.x + threadIdx.x;
    float v = pv[i], mn = v, mx = v;
    #pragma unroll
    for (int o = 16; o > 0; o >>= 1) {
        mn = fminf(mn, __shfl_xor_sync(0xFFFFFFFFu, mn, o));
        mx = fmaxf(mx, __shfl_xor_sync(0xFFFFFFFFu, mx, o));
    }
    if ((threadIdx.x & 31) == 0) { atomicMin(&g_pvmin_e, encf(mn)); atomicMax(&g_pvmax_e, encf(mx)); }
}

// ---------------- fused GEMM (mma.sync bf16 + ldmatrix) + epilogue ----------------
__device__ __forceinline__ void load_panel(uint32_t sdst, const __nv_bfloat16* zrow0, int tid) {
    const char* g = (const char*)zrow0;
    #pragma unroll
    for (int i = 0; i < 4; i++) {
        int seg = tid + i * NTHREADS;          // 4096 16B segments
        int row = seg >> 5, c16 = seg & 31;
        CP16(sdst + row * RS + c16 * 16, g + row * 512 + c16 * 16);
    }
}

__global__ void __launch_bounds__(NTHREADS, 1) k_sim() {
    extern __shared__ __align__(16) char smem[];
    const int tid = threadIdx.x, w = tid >> 5, lane = tid & 31;
    const int bc = blockIdx.x;                 // 0..1 : 4096-col chunk
    const int bm = blockIdx.y;                 // 0..63: 128-row stripe
    const int wr = w & 7, wc = w >> 3;         // 16-row band (0..7), 32-col quarter (0..3)
    const uint32_t sbase = smem_u32(smem);
    const uint32_t sA = sbase, sB0 = sbase + TILE_B, sB1 = sbase + 2 * TILE_B;

    load_panel(sA, g_zb + (size_t)(bm * 128) * ND, tid);
    load_panel(sB0, g_zb + (size_t)(bc * 4096) * ND, tid);
    CP_COMMIT();
    load_panel(sB1, g_zb + (size_t)(bc * 4096 + 128) * ND, tid);
    CP_COMMIT();

    const float it = g_it;
    const int rowbase = bm * 128 + wr * 16;
    const uint32_t offA = (uint32_t)(wr * 16 + (lane & 15)) * RS + (uint32_t)(lane >> 4) * 16;
    const uint32_t offB = (uint32_t)(wc * 32 + ((lane >> 4) & 1) * 8 + (lane & 7)) * RS
                        + (uint32_t)((lane >> 3) & 1) * 16;

    float spd[2], sng[2], tng[2];
    #pragma unroll
    for (int h = 0; h < 2; h++) { spd[h] = 0.f; sng[h] = 0.f; tng[h] = 0.f; }
    float mn = 1e30f, mx = -1e30f;

    for (int t = 0; t < 32; t++) {
        if (t < 30) { CP_WAIT(1); } else { CP_WAIT(0); }
        __syncthreads();
        const uint32_t sB = (t & 1) ? sB1 : sB0;

        float acc[4][4];
        #pragma unroll
        for (int n = 0; n < 4; n++)
            #pragma unroll
            for (int q = 0; q < 4; q++) acc[n][q] = 0.f;

        #pragma unroll
        for (int kk = 0; kk < 16; kk++) {
            uint32_t a0, a1, a2, a3;
            LDSM4(a0, a1, a2, a3, sA + offA + (uint32_t)kk * 32);
            uint32_t b0[4], b1[4];
            #pragma unroll
            for (int p = 0; p < 2; p++)
                LDSM4(b0[2 * p], b1[2 * p], b0[2 * p + 1], b1[2 * p + 1],
                      sB + offB + (uint32_t)p * (16 * RS) + (uint32_t)kk * 32);
            #pragma unroll
            for (int n = 0; n < 4; n++)
                MMA(acc[n], a0, a1, a2, a3, b0[n], b1[n]);
        }

        __syncthreads();
        if (t + 2 < 32) {
            load_panel((t & 1) ? sB1 : sB0,
                       g_zb + (size_t)(bc * 4096 + (t + 2) * 128) * ND, tid);
            CP_COMMIT();
        }

        // ---- epilogue on registers ----
        const int colbase = bc * 4096 + t * 128 + wc * 32 + (lane & 3) * 2;
        #pragma unroll
        for (int n = 0; n < 4; n++) {
            #pragma unroll
            for (int h = 0; h < 2; h++) {
                int row = rowbase + (lane >> 2) + h * 8;
                #pragma unroll
                for (int q = 0; q < 2; q++) {
                    int col = colbase + n * 8 + q;
                    float v = acc[n][h * 2 + q];
                    float s = fmaf(v, it, -it);
                    float e = __expf(s);
                    unsigned d = (unsigned)(col - row) & 8191u;
                    if (d == 0u) {
                        spd[h] += e;
                    } else if (d <= 8u) {
                        spd[h] += e;
                        g_pos_s[row * NPOS + d - 1] = s;
                    } else {
                        sng[h] += e;
                        tng[h] = fmaf(s, e, tng[h]);
                        mn = fminf(mn, s); mx = fmaxf(mx, s);
                    }
                }
            }
        }
    }

    // reduce the 4 lanes (lane&3) sharing each row
    const int sidx = bc * 4 + wc;
    #pragma unroll
    for (int h = 0; h < 2; h++) {
        float a0 = spd[h], a1 = sng[h], a2 = tng[h];
        a0 += __shfl_down_sync(0xFFFFFFFFu, a0, 2, 4);
        a0 += __shfl_down_sync(0xFFFFFFFFu, a0, 1, 4);
        a1 += __shfl_down_sync(0xFFFFFFFFu, a1, 2, 4);
        a1 += __shfl_down_sync(0xFFFFFFFFu, a1, 1, 4);
        a2 += __shfl_down_sync(0xFFFFFFFFu, a2, 2, 4);
        a2 += __shfl_down_sync(0xFFFFFFFFu, a2, 1, 4);
        if ((lane & 3) == 0) {
            int row = rowbase + (lane >> 2) + h * 8;
            g_pSpd [sidx * NB + row] = a0;
            g_pSneg[sidx * NB + row] = a1;
            g_pTneg[sidx * NB + row] = a2;
        }
    }
    #pragma unroll
    for (int o = 16; o > 0; o >>= 1) {
        mn = fminf(mn, __shfl_xor_sync(0xFFFFFFFFu, mn, o));
        mx = fmaxf(mx, __shfl_xor_sync(0xFFFFFFFFu, mx, o));
    }
    if (lane == 0) { atomicMin(&g_negmin_e, encf(mn)); atomicMax(&g_negmax_e, encf(mx)); }
}

__global__ void k_lse() {
    int i = blockIdx.x * blockDim.x + threadIdx.x;
    float spd = 0.f, sn = 0.f, tn = 0.f;
    #pragma unroll
    for (int t = 0; t < 8; t++) {
        spd += g_pSpd [t * NB + i];
        sn  += g_pSneg[t * NB + i];
        tn  += g_pTneg[t * NB + i];
    }
    float nmin = decf2(g_negmin_e), nmax = decf2(g_negmax_e);
    float a = 1.0f / (nmax - nmin + 1e-8f);
    float b = 1.0f - nmin * a;
    g_lse[i] = logf(spd + a * tn + b * sn);
}

__global__ void k_final(const float* __restrict__ pv, float* __restrict__ out) {
    const int tid = threadIdx.x;
    float vmin = decf2(g_pvmin_e), vmax = decf2(g_pvmax_e);
    float wmin = 1.0f - vmax, wmax = 1.0f - vmin;
    float inv = 1.0f / (wmax - wmin + 1e-8f);
    float local = 0.f;
    for (int idx = tid; idx < NB * NPOS; idx += 1024) {
        float pw = ((1.0f - pv[idx]) - wmin) * inv;
        local += (g_pos_s[idx] - g_lse[idx >> 3]) * pw;
    }
    __shared__ float red[1024];
    red[tid] = local;
    __syncthreads();
    for (int s = 512; s > 0; s >>= 1) {
        if (tid < s) red[tid] += red[tid + s];
        __syncthreads();
    }
    if (tid == 0) out[0] = -red[0] * (1.0f / (float)(NB * NPOS));
}

// ---------------- launch ----------------
extern "C" void kernel_launch(void* const* d_in, const int* in_sizes, int n_in,
                              void* d_out, int out_size) {
    const float* emb  = (const float*)d_in[0];
    const float* pv   = (const float*)d_in[1];
    const float* temp = (const float*)d_in[2];
    float* out = (float*)d_out;

    const int SMEM = 3 * TILE_B;               // 202752 B
    cudaFuncSetAttribute(k_sim, cudaFuncAttributeMaxDynamicSharedMemorySize, SMEM);

    k_init<<<1, 1>>>(temp);
    k_norm<<<NB, ND>>>(emb);
    k_pvminmax<<<(NB * NPOS) / 1024, 1024>>>(pv);
    dim3 grid(2, 64);
    k_sim<<<grid, NTHREADS, SMEM>>>();
    k_lse<<<NB / 256, 256>>>();
    k_final<<<1, 1024>>>(pv, out);
}

// round 12
// speedup vs baseline: 1.1139x; 1.1139x over previous
#include <cuda_runtime.h>
#include <cuda_bf16.h>
#include <math.h>
#include <stdint.h>

#define NB 8192
#define ND 256
#define NPOS 8
#define RS 528           // smem row stride bytes (256 bf16 + 8 pad)
#define TILE_B (128 * RS)
#define NTHREADS 512

__device__ __align__(16) __nv_bfloat16 g_zb[NB * ND];
__device__ float g_pSpd[4 * NB], g_pSneg[4 * NB], g_pTneg[4 * NB];
__device__ float g_pos_s[NB * NPOS], g_lse[NB];
__device__ float g_fpart[64];
__device__ float g_it;
__device__ unsigned g_negmin_e, g_negmax_e, g_pvmin_e, g_pvmax_e;

__device__ __forceinline__ unsigned encf(float f) {
    unsigned u = __float_as_uint(f);
    return (u & 0x80000000u) ? ~u : (u | 0x80000000u);
}
__device__ __forceinline__ float decf2(unsigned e) {
    unsigned u = (e & 0x80000000u) ? (e ^ 0x80000000u) : ~e;
    return __uint_as_float(u);
}

#define CP16(s, g)  asm volatile("cp.async.cg.shared.global [%0], [%1], 16;" :: "r"(s), "l"(g))
#define CP_COMMIT() asm volatile("cp.async.commit_group;" ::: "memory")
#define CP_WAIT(n)  asm volatile("cp.async.wait_group %0;" :: "n"(n) : "memory")

__device__ __forceinline__ uint32_t smem_u32(const void* p) {
    uint32_t a;
    asm("{ .reg .u64 t; cvta.to.shared.u64 t, %1; cvt.u32.u64 %0, t; }" : "=r"(a) : "l"(p));
    return a;
}

#define LDSM4(r0, r1, r2, r3, a) \
    asm volatile("ldmatrix.sync.aligned.m8n8.x4.shared.b16 {%0,%1,%2,%3}, [%4];" \
        : "=r"(r0), "=r"(r1), "=r"(r2), "=r"(r3) : "r"(a))

#define MMA(d, A0, A1, A2, A3, B0, B1) \
    asm volatile("mma.sync.aligned.m16n8k16.row.col.f32.bf16.bf16.f32 " \
        "{%0,%1,%2,%3},{%4,%5,%6,%7},{%8,%9},{%0,%1,%2,%3};" \
        : "+f"((d)[0]), "+f"((d)[1]), "+f"((d)[2]), "+f"((d)[3]) \
        : "r"(A0), "r"(A1), "r"(A2), "r"(A3), "r"(B0), "r"(B1))

// ---------------- small kernels ----------------
__global__ void k_norm(const float* __restrict__ emb, const float* __restrict__ temp) {
    int row = blockIdx.x, t = threadIdx.x;
    if (row == 0 && t == 0) {
        float sp = log1pf(expf(temp[0]));
        g_it = 1.0f / sp;
        g_negmin_e = 0xFFFFFFFFu; g_negmax_e = 0u;
        g_pvmin_e = 0xFFFFFFFFu;  g_pvmax_e = 0u;
    }
    float x = emb[row * ND + t];
    float s = x * x;
    #pragma unroll
    for (int o = 16; o > 0; o >>= 1) s += __shfl_xor_sync(0xFFFFFFFFu, s, o);
    __shared__ float ws[8];
    if ((t & 31) == 0) ws[t >> 5] = s;
    __syncthreads();
    float tot = 0.f;
    #pragma unroll
    for (int i = 0; i < 8; i++) tot += ws[i];
    g_zb[row * ND + t] = __float2bfloat16(x / fmaxf(sqrtf(tot), 1e-12f));
}

__global__ void k_pvminmax(const float* __restrict__ pv) {
    int i = blockIdx.x * blockDim.x + threadIdx.x;
    float v = pv[i], mn = v, mx = v;
    #pragma unroll
    for (int o = 16; o > 0; o >>= 1) {
        mn = fminf(mn, __shfl_xor_sync(0xFFFFFFFFu, mn, o));
        mx = fmaxf(mx, __shfl_xor_sync(0xFFFFFFFFu, mx, o));
    }
    if ((threadIdx.x & 31) == 0) { atomicMin(&g_pvmin_e, encf(mn)); atomicMax(&g_pvmax_e, encf(mx)); }
}

// ---------------- fused GEMM (A-resident mma.sync bf16) + epilogue ----------------
__device__ __forceinline__ void load_panel(uint32_t sdst, const __nv_bfloat16* zrow0, int tid) {
    const char* g = (const char*)zrow0;
    #pragma unroll
    for (int i = 0; i < 8; i++) {
        int seg = tid + i * NTHREADS;          // 4096 16B segments
        int row = seg >> 5, c16 = seg & 31;
        CP16(sdst + row * RS + c16 * 16, g + row * 512 + c16 * 16);
    }
}

__global__ void __launch_bounds__(NTHREADS, 1) k_sim() {
    extern __shared__ __align__(16) char smem[];
    const int tid = threadIdx.x, w = tid >> 5, lane = tid & 31;
    const int bc = blockIdx.x;                 // 0..1 : 4096-col chunk
    const int bm = blockIdx.y;                 // 0..63: 128-row stripe
    const int wr = w & 7, wc = w >> 3;         // 16-row band (0..7), 64-col half (0..1)
    const uint32_t sbase = smem_u32(smem);
    const uint32_t sA = sbase, sB0 = sbase + TILE_B, sB1 = sbase + 2 * TILE_B;

    load_panel(sA, g_zb + (size_t)(bm * 128) * ND, tid);
    CP_COMMIT();
    load_panel(sB0, g_zb + (size_t)(bc * 4096) * ND, tid);
    CP_COMMIT();
    load_panel(sB1, g_zb + (size_t)(bc * 4096 + 128) * ND, tid);
    CP_COMMIT();

    const float it = g_it;
    const int rowbase = bm * 128 + wr * 16;
    const uint32_t offA = (uint32_t)(wr * 16 + (lane & 15)) * RS + (uint32_t)(lane >> 4) * 16;
    const uint32_t offB = (uint32_t)(wc * 64 + ((lane >> 4) & 1) * 8 + (lane & 7)) * RS
                        + (uint32_t)((lane >> 3) & 1) * 16;

    // hoist A fragments: constant across all 32 B tiles
    CP_WAIT(2);
    __syncthreads();
    uint32_t a_frag[16][4];
    #pragma unroll
    for (int kk = 0; kk < 16; kk++)
        LDSM4(a_frag[kk][0], a_frag[kk][1], a_frag[kk][2], a_frag[kk][3],
              sA + offA + (uint32_t)kk * 32);

    float spd[2], sng[2], tng[2];
    #pragma unroll
    for (int h = 0; h < 2; h++) { spd[h] = 0.f; sng[h] = 0.f; tng[h] = 0.f; }
    float mn = 1e30f, mx = -1e30f;

    for (int t = 0; t < 32; t++) {
        if (t < 30) { CP_WAIT(1); } else { CP_WAIT(0); }
        __syncthreads();
        const uint32_t sB = (t & 1) ? sB1 : sB0;

        float acc[8][4];
        #pragma unroll
        for (int n = 0; n < 8; n++)
            #pragma unroll
            for (int q = 0; q < 4; q++) acc[n][q] = 0.f;

        #pragma unroll
        for (int kk = 0; kk < 16; kk++) {
            uint32_t b0[8], b1[8];
            #pragma unroll
            for (int p = 0; p < 4; p++)
                LDSM4(b0[2 * p], b1[2 * p], b0[2 * p + 1], b1[2 * p + 1],
                      sB + offB + (uint32_t)p * (16 * RS) + (uint32_t)kk * 32);
            #pragma unroll
            for (int n = 0; n < 8; n++)
                MMA(acc[n], a_frag[kk][0], a_frag[kk][1], a_frag[kk][2], a_frag[kk][3],
                    b0[n], b1[n]);
        }

        __syncthreads();
        if (t + 2 < 32) {
            load_panel((t & 1) ? sB1 : sB0,
                       g_zb + (size_t)(bc * 4096 + (t + 2) * 128) * ND, tid);
            CP_COMMIT();
        }

        // ---- epilogue on registers ----
        const int colbase = bc * 4096 + t * 128 + wc * 64 + (lane & 3) * 2;
        #pragma unroll
        for (int n = 0; n < 8; n++) {
            #pragma unroll
            for (int h = 0; h < 2; h++) {
                int row = rowbase + (lane >> 2) + h * 8;
                #pragma unroll
                for (int q = 0; q < 2; q++) {
                    int col = colbase + n * 8 + q;
                    float v = acc[n][h * 2 + q];
                    float s = fmaf(v, it, -it);
                    float e = __expf(s);
                    unsigned d = (unsigned)(col - row) & 8191u;
                    if (d == 0u) {
                        spd[h] += e;
                    } else if (d <= 8u) {
                        spd[h] += e;
                        g_pos_s[row * NPOS + d - 1] = s;
                    } else {
                        sng[h] += e;
                        tng[h] = fmaf(s, e, tng[h]);
                        mn = fminf(mn, s); mx = fmaxf(mx, s);
                    }
                }
            }
        }
    }

    // reduce the 4 lanes (lane&3) sharing each row
    const int sidx = bc * 2 + wc;
    #pragma unroll
    for (int h = 0; h < 2; h++) {
        float a0 = spd[h], a1 = sng[h], a2 = tng[h];
        a0 += __shfl_down_sync(0xFFFFFFFFu, a0, 2, 4);
        a0 += __shfl_down_sync(0xFFFFFFFFu, a0, 1, 4);
        a1 += __shfl_down_sync(0xFFFFFFFFu, a1, 2, 4);
        a1 += __shfl_down_sync(0xFFFFFFFFu, a1, 1, 4);
        a2 += __shfl_down_sync(0xFFFFFFFFu, a2, 2, 4);
        a2 += __shfl_down_sync(0xFFFFFFFFu, a2, 1, 4);
        if ((lane & 3) == 0) {
            int row = rowbase + (lane >> 2) + h * 8;
            g_pSpd [sidx * NB + row] = a0;
            g_pSneg[sidx * NB + row] = a1;
            g_pTneg[sidx * NB + row] = a2;
        }
    }
    #pragma unroll
    for (int o = 16; o > 0; o >>= 1) {
        mn = fminf(mn, __shfl_xor_sync(0xFFFFFFFFu, mn, o));
        mx = fmaxf(mx, __shfl_xor_sync(0xFFFFFFFFu, mx, o));
    }
    if (lane == 0) { atomicMin(&g_negmin_e, encf(mn)); atomicMax(&g_negmax_e, encf(mx)); }
}

__global__ void k_lse() {
    int i = blockIdx.x * blockDim.x + threadIdx.x;
    float spd = 0.f, sn = 0.f, tn = 0.f;
    #pragma unroll
    for (int t = 0; t < 4; t++) {
        spd += g_pSpd [t * NB + i];
        sn  += g_pSneg[t * NB + i];
        tn  += g_pTneg[t * NB + i];
    }
    float nmin = decf2(g_negmin_e), nmax = decf2(g_negmax_e);
    float a = 1.0f / (nmax - nmin + 1e-8f);
    float b = 1.0f - nmin * a;
    g_lse[i] = logf(spd + a * tn + b * sn);
}

__global__ void k_final1(const float* __restrict__ pv) {
    const int tid = threadIdx.x, b = blockIdx.x;      // 64 blocks x 256 threads
    float vmin = decf2(g_pvmin_e), vmax = decf2(g_pvmax_e);
    float wmin = 1.0f - vmax, wmax = 1.0f - vmin;
    float inv = 1.0f / (wmax - wmin + 1e-8f);
    float local = 0.f;
    int base = b * 1024;
    for (int k = tid; k < 1024; k += 256) {
        int idx = base + k;
        float pw = ((1.0f - pv[idx]) - wmin) * inv;
        local += (g_pos_s[idx] - g_lse[idx >> 3]) * pw;
    }
    __shared__ float red[256];
    red[tid] = local;
    __syncthreads();
    for (int s = 128; s > 0; s >>= 1) {
        if (tid < s) red[tid] += red[tid + s];
        __syncthreads();
    }
    if (tid == 0) g_fpart[b] = red[0];
}

__global__ void k_final2(float* __restrict__ out) {
    float s = 0.f;
    #pragma unroll
    for (int i = 0; i < 64; i++) s += g_fpart[i];
    out[0] = -s * (1.0f / (float)(NB * NPOS));
}

// ---------------- launch ----------------
extern "C" void kernel_launch(void* const* d_in, const int* in_sizes, int n_in,
                              void* d_out, int out_size) {
    const float* emb  = (const float*)d_in[0];
    const float* pv   = (const float*)d_in[1];
    const float* temp = (const float*)d_in[2];
    float* out = (float*)d_out;

    const int SMEM = 3 * TILE_B;               // 202752 B
    cudaFuncSetAttribute(k_sim, cudaFuncAttributeMaxDynamicSharedMemorySize, SMEM);

    k_norm<<<NB, ND>>>(emb, temp);
    k_pvminmax<<<(NB * NPOS) / 1024, 1024>>>(pv);
    dim3 grid(2, 64);
    k_sim<<<grid, NTHREADS, SMEM>>>();
    k_lse<<<NB / 256, 256>>>();
    k_final1<<<64, 256>>>(pv);
    k_final2<<<1, 1>>>(out);
}